// round 15
// baseline (speedup 1.0000x reference)
#include <cuda_runtime.h>
#include <cuda_bf16.h>

// LSTM: SEQ=512, BATCH=4096, INPUT=1, HIDDEN=100, OUTPUT=1
// R8 lesson: broadcast LDS.128 costs ~2 crossbar phases -> LDS-bound at
// ~20.8K wf/step (fma only 38%). Fix: split weight streams between the smem
// crossbar (LDS) and the LSU/L1TEX path (LDG from L1D-resident __device__
// arrays), and raise to 16 warps (4/SMSP) for latency hiding.
// lane = batch element (32/CTA, 128 CTAs); c in regs; h ping-pong in SMEM;
// fma.rn.f32x2 inner loop, gates packed (i,f),(g,o).

#define T_SEQ 512
#define B_TOT 4096
#define H 100
#define TILE_B 32
#define NWARP 16
#define NTHR (NWARP * 32)

// unit partition: warps 0-3 own 7 units, warps 4-15 own 6 (28+72=100)
// per-warp weight split: smem-units 4 (w<4) or 3 (w>=4), ldg-units 3
#define SW_TOT 52   // total smem-resident units
#define GW_TOT 48   // total ldg-resident units

typedef unsigned long long u64;

// weight arrays repacked by a prologue kernel (graph-capturable, no alloc)
__device__ ulonglong2 g_sWp[H * SW_TOT];  // [k*52 + su]  -> smem copy
__device__ ulonglong2 g_gWp[H * GW_TOT];  // [k*48 + gu]  -> read via LDG

// SMEM layout (bytes)
#define OFF_SWP   0
#define OFF_BP    (H * SW_TOT * 16)            // 83200
#define OFF_WIH   (OFF_BP + 16 * H)            // 84800
#define OFF_WL    (OFF_WIH + 16 * H)           // 86400
#define OFF_HBUF  (OFF_WL + 4 * H)             // 86800
#define SMEM_BYTES (OFF_HBUF + 2 * H * TILE_B * 4)  // 112400

__device__ __forceinline__ u64 pack2(float lo, float hi) {
    u64 r;
    asm("mov.b64 %0, {%1, %2};" : "=l"(r)
        : "r"(__float_as_uint(lo)), "r"(__float_as_uint(hi)));
    return r;
}
__device__ __forceinline__ void unpack2(u64 v, float& lo, float& hi) {
    unsigned int a, b;
    asm("mov.b64 {%0, %1}, %2;" : "=r"(a), "=r"(b) : "l"(v));
    lo = __uint_as_float(a);
    hi = __uint_as_float(b);
}
#if __CUDACC_VER_MAJOR__ >= 13
__device__ __forceinline__ u64 ffma2(u64 a, u64 b, u64 c) {
    u64 d;
    asm("fma.rn.f32x2 %0, %1, %2, %3;" : "=l"(d) : "l"(a), "l"(b), "l"(c));
    return d;
}
#else
__device__ __forceinline__ u64 ffma2(u64 a, u64 b, u64 c) {
    float alo, ahi, blo, bhi, clo, chi;
    unpack2(a, alo, ahi); unpack2(b, blo, bhi); unpack2(c, clo, chi);
    return pack2(fmaf(alo, blo, clo), fmaf(ahi, bhi, chi));
}
#endif

__device__ __forceinline__ float sigf(float x) {
    return __fdividef(1.0f, 1.0f + __expf(-x));
}
__device__ __forceinline__ float tanhacc(float x) {
    return __fdividef(2.0f, 1.0f + __expf(-2.0f * x)) - 1.0f;
}

// ---- repack kernel: W_hh -> g_sWp / g_gWp (gate pairs (i,f),(g,o)) ----
__global__ void repack_kernel(const float* __restrict__ W_hh) {
    int idx = blockIdx.x * blockDim.x + threadIdx.x;  // over H*H = 10000
    if (idx >= H * H) return;
    int k = idx / H;
    int t = idx - k * H;  // unit index 0..99 (contiguous across warps)
    // invert unit partition: which warp, which j
    int w, j;
    if (t < 28) { w = t / 7; j = t - 7 * w; }
    else { int r = t - 28; w = 4 + r / 6; j = r - 6 * (w - 4); }
    int sc  = (w < 4) ? 4 : 3;
    int su0 = (w < 4) ? 4 * w : 16 + 3 * (w - 4);
    int gu0 = (w < 4) ? 3 * w : 12 + 3 * (w - 4);
    ulonglong2 v;
    v.x = pack2(W_hh[(0 * H + t) * H + k], W_hh[(1 * H + t) * H + k]);
    v.y = pack2(W_hh[(2 * H + t) * H + k], W_hh[(3 * H + t) * H + k]);
    if (j < sc) g_sWp[k * SW_TOT + su0 + j] = v;
    else        g_gWp[k * GW_TOT + gu0 + (j - sc)] = v;
}

// ---- one LSTM step for SC smem-units + GC ldg-units ----
template <int SC, int GC>
__device__ __forceinline__ void lstm_step(
    const ulonglong2* __restrict__ sW,   // smem base + su0
    const ulonglong2* __restrict__ gW,   // global base + gu0
    const ulonglong2* __restrict__ bp,
    const ulonglong2* __restrict__ wih,
    const float* __restrict__ hread,
    float* __restrict__ hwrite,
    u64 xp, float* c, int ubase, int lane)
{
    u64 acc0[SC + GC], acc1[SC + GC];
#pragma unroll
    for (int j = 0; j < SC + GC; ++j) {
        ulonglong2 bb = bp[ubase + j];
        ulonglong2 wi = wih[ubase + j];
        acc0[j] = ffma2(xp, wi.x, bb.x);
        acc1[j] = ffma2(xp, wi.y, bb.y);
    }
#pragma unroll 2
    for (int k = 0; k < H; ++k) {
        const float hk = hread[k * TILE_B + lane];
        const u64 hp = pack2(hk, hk);
        const ulonglong2* __restrict__ srow = sW + k * SW_TOT;
        const ulonglong2* __restrict__ grow = gW + k * GW_TOT;
#pragma unroll
        for (int j = 0; j < GC; ++j) {   // issue LDGs first (longer latency)
            ulonglong2 w = __ldg(grow + j);
            acc0[SC + j] = ffma2(w.x, hp, acc0[SC + j]);
            acc1[SC + j] = ffma2(w.y, hp, acc1[SC + j]);
        }
#pragma unroll
        for (int j = 0; j < SC; ++j) {
            ulonglong2 w = srow[j];
            acc0[j] = ffma2(w.x, hp, acc0[j]);
            acc1[j] = ffma2(w.y, hp, acc1[j]);
        }
    }
#pragma unroll
    for (int j = 0; j < SC + GC; ++j) {
        float gi, gf, gg, go;
        unpack2(acc0[j], gi, gf);
        unpack2(acc1[j], gg, go);
        float ig = sigf(gi);
        float fg = sigf(gf);
        float g  = tanhacc(gg);
        float og = sigf(go);
        float cn = fmaf(fg, c[j], ig * g);
        c[j] = cn;
        hwrite[(ubase + j) * TILE_B + lane] = og * tanhacc(cn);
    }
}

__global__ void __launch_bounds__(NTHR, 1)
lstm_kernel(const float* __restrict__ X,      // [T, B]
            const float* __restrict__ W_ih,   // [4H, 1]
            const float* __restrict__ b_ih,   // [4H]
            const float* __restrict__ b_hh,   // [4H]
            const float* __restrict__ W_lin,  // [1, H]
            const float* __restrict__ b_lin,  // [1]
            float* __restrict__ out)          // [B, 1]
{
    extern __shared__ char smem[];
    ulonglong2* sWp = (ulonglong2*)(smem + OFF_SWP);
    ulonglong2* bp  = (ulonglong2*)(smem + OFF_BP);
    ulonglong2* wih = (ulonglong2*)(smem + OFF_WIH);
    float*      wl  = (float*)(smem + OFF_WL);
    float*      hb  = (float*)(smem + OFF_HBUF);

    const int tid  = threadIdx.x;
    const int lane = tid & 31;
    const int warp = tid >> 5;
    const int bglob = blockIdx.x * TILE_B + lane;
    const int ubase = (warp < 4) ? 7 * warp : 28 + 6 * (warp - 4);
    const int su0   = (warp < 4) ? 4 * warp : 16 + 3 * (warp - 4);
    const int gu0   = (warp < 4) ? 3 * warp : 12 + 3 * (warp - 4);

    // ---- prologue ----
    for (int i = tid; i < H * SW_TOT; i += NTHR)
        sWp[i] = g_sWp[i];
    for (int u = tid; u < H; u += NTHR) {
        ulonglong2 bb, wi;
        bb.x = pack2(b_ih[0 * H + u] + b_hh[0 * H + u],
                     b_ih[1 * H + u] + b_hh[1 * H + u]);
        bb.y = pack2(b_ih[2 * H + u] + b_hh[2 * H + u],
                     b_ih[3 * H + u] + b_hh[3 * H + u]);
        bp[u] = bb;
        wi.x = pack2(W_ih[0 * H + u], W_ih[1 * H + u]);
        wi.y = pack2(W_ih[2 * H + u], W_ih[3 * H + u]);
        wih[u] = wi;
        wl[u] = W_lin[u];
    }
    for (int i = tid; i < H * TILE_B; i += NTHR)
        hb[i] = 0.0f;
    __syncthreads();

    // ---- recurrence ----
    float c[7];
#pragma unroll
    for (int i = 0; i < 7; ++i) c[i] = 0.0f;

    const ulonglong2* sW = sWp + su0;
    const ulonglong2* gW = g_gWp + gu0;

    int p = 0;
    float xcur = X[bglob];
    for (int t = 0; t < T_SEQ; ++t) {
        float xnext = (t + 1 < T_SEQ) ? X[(t + 1) * B_TOT + bglob] : 0.0f;
        const u64 xp = pack2(xcur, xcur);
        const float* __restrict__ hread = hb + p * (H * TILE_B);
        float* __restrict__ hwrite = hb + (p ^ 1) * (H * TILE_B);

        if (warp < 4)
            lstm_step<4, 3>(sW, gW, bp, wih, hread, hwrite, xp, c, ubase, lane);
        else
            lstm_step<3, 3>(sW, gW, bp, wih, hread, hwrite, xp, c, ubase, lane);

        __syncthreads();
        p ^= 1;
        xcur = xnext;
    }

    // ---- linear head (warp 0) ----
    if (warp == 0) {
        const float* hfin = hb + p * (H * TILE_B);
        float acc = b_lin[0];
#pragma unroll 4
        for (int k = 0; k < H; ++k)
            acc = fmaf(hfin[k * TILE_B + lane], wl[k], acc);
        out[bglob] = acc;
    }
}

extern "C" void kernel_launch(void* const* d_in, const int* in_sizes, int n_in,
                              void* d_out, int out_size) {
    const float* X     = (const float*)d_in[0];
    const float* W_ih  = (const float*)d_in[1];
    const float* W_hh  = (const float*)d_in[2];
    const float* b_ih  = (const float*)d_in[3];
    const float* b_hh  = (const float*)d_in[4];
    const float* W_lin = (const float*)d_in[5];
    const float* b_lin = (const float*)d_in[6];
    float* out = (float*)d_out;

    repack_kernel<<<(H * H + 255) / 256, 256>>>(W_hh);

    cudaFuncSetAttribute(lstm_kernel,
                         cudaFuncAttributeMaxDynamicSharedMemorySize,
                         SMEM_BYTES);
    lstm_kernel<<<B_TOT / TILE_B, NTHR, SMEM_BYTES>>>(
        X, W_ih, b_ih, b_hh, W_lin, b_lin, out);
}